// round 15
// baseline (speedup 1.0000x reference)
#include <cuda_runtime.h>
#include <cuda_fp16.h>

// ---------------------------------------------------------------------------
// out[m,n] = sum_r sum_k A[r,m,k] * W[r,n,k]   (M=N=4096, K=8*1024)
// fp32 in/out, fp16 single-pass mma.sync.m16n8k16 (f32 accumulate).
// R15: two CTAs per SM (independent barrier domains) to overlap one CTA's
// sync/wait idle with the other's MMA stream. Per-CTA shape = R11's proven
// 128x128 / 8 warps of 64x32 (116 regs), 3-stage cp.async.cg ring
// (96KB smem/CTA so two CTAs fit), split-K=2 (R14-validated) -> grid 2048.
// ---------------------------------------------------------------------------

using u32 = unsigned int;

static constexpr int NT      = 4096;       // N total (also M total)
static constexpr int KL      = 1024;       // K per rank slab
static constexpr int NCH_H   = 64;         // chunks per split (half of 128)
static constexpr int R_B     = 16384;      // B region offset within a stage
static constexpr int STAGE   = 32768;      // A 16KB + B 16KB (fp16)
static constexpr int NSTG    = 3;
static constexpr int SMEM_TOTAL = NSTG * STAGE;          // 96 KB
static constexpr size_t NA   = (size_t)8 * NT * KL;      // elems per tensor

// fp16 scratch: A at [0, NA), W at [NA, 2*NA)  (128 MB)
__device__ __half g_fp16[2 * NA];

// ---------------- convert pass ----------------
__global__ __launch_bounds__(256) void cvt_kernel(const float* __restrict__ A,
                                                  const float* __restrict__ W)
{
    const size_t total8 = (2 * NA) / 8;
    const size_t stride = (size_t)gridDim.x * blockDim.x;
    for (size_t g = (size_t)blockIdx.x * blockDim.x + threadIdx.x;
         g < total8; g += stride) {
        const size_t off = g * 8;
        const float* src = (off < NA) ? (A + off) : (W + (off - NA));
        const float4 v0 = *reinterpret_cast<const float4*>(src);
        const float4 v1 = *reinterpret_cast<const float4*>(src + 4);
        const __half2 h0 = __floats2half2_rn(v0.x, v0.y);
        const __half2 h1 = __floats2half2_rn(v0.z, v0.w);
        const __half2 h2 = __floats2half2_rn(v1.x, v1.y);
        const __half2 h3 = __floats2half2_rn(v1.z, v1.w);
        uint4 pk;
        pk.x = *(const u32*)&h0; pk.y = *(const u32*)&h1;
        pk.z = *(const u32*)&h2; pk.w = *(const u32*)&h3;
        *reinterpret_cast<uint4*>(&g_fp16[off]) = pk;
    }
}

// ---------------- zero the output (harness poisons it) ----------------
__global__ __launch_bounds__(256) void zero_kernel(float4* __restrict__ out4)
{
    const size_t total = (size_t)NT * NT / 4;
    const size_t stride = (size_t)gridDim.x * blockDim.x;
    for (size_t g = (size_t)blockIdx.x * blockDim.x + threadIdx.x;
         g < total; g += stride)
        out4[g] = make_float4(0.f, 0.f, 0.f, 0.f);
}

// ---------------- GEMM ----------------
static __device__ __forceinline__ u32 smem_u32(const void* p) {
    u32 a;
    asm("{ .reg .u64 t; cvta.to.shared.u64 t, %1; cvt.u32.u64 %0, t; }"
        : "=r"(a) : "l"(p));
    return a;
}

static __device__ __forceinline__ void ldsm4(u32 addr, u32* r) {
    asm volatile("ldmatrix.sync.aligned.m8n8.x4.shared.b16 {%0,%1,%2,%3}, [%4];"
                 : "=r"(r[0]), "=r"(r[1]), "=r"(r[2]), "=r"(r[3]) : "r"(addr));
}

static __device__ __forceinline__ void mma16816(float* c, const u32* a,
                                                u32 b0, u32 b1) {
    asm volatile(
        "mma.sync.aligned.m16n8k16.row.col.f32.f16.f16.f32 "
        "{%0,%1,%2,%3}, {%4,%5,%6,%7}, {%8,%9}, {%0,%1,%2,%3};"
        : "+f"(c[0]), "+f"(c[1]), "+f"(c[2]), "+f"(c[3])
        : "r"(a[0]), "r"(a[1]), "r"(a[2]), "r"(a[3]), "r"(b0), "r"(b1));
}

static __device__ __forceinline__ void cp16(u32 sdst, const void* gsrc) {
    asm volatile("cp.async.cg.shared.global [%0], [%1], 16;"
                 :: "r"(sdst), "l"(gsrc) : "memory");
}

__global__ __launch_bounds__(256, 2)
void gemm_rs_kernel(float* __restrict__ out)
{
    extern __shared__ char smem[];
    const u32 sb  = smem_u32(smem);
    const int tid = threadIdx.x;
    const int lane = tid & 31;
    const int w    = tid >> 5;

    // Grid: 2048 = 1024 tiles x 2 K-splits. Tile raster: groups of
    // 8 M-tiles x 32 N-tiles (wave working set well under L2).
    const int lin   = blockIdx.x & 1023;
    const int split = blockIdx.x >> 10;        // 0 or 1
    const int grp = lin >> 8;                  // 0..3
    const int rem = lin & 255;
    const int m0  = ((grp << 3) + (rem & 7)) << 7;   // * 128
    const int n0  = (rem >> 3) << 7;                 // * 128
    const int ic0 = split * NCH_H;             // global chunk base

    // ---- cp.async thread map: row = tid>>1, 4 consecutive 16B chunks ----
    const int cRow = tid >> 1;                 // 0..127
    const int jb   = (tid & 1) << 2;           // 0 or 4 (16B-chunk index)
    const __half* gA = g_fp16 + (size_t)(m0 + cRow) * KL + (size_t)jb * 8;
    const __half* gB = g_fp16 + NA + (size_t)(n0 + cRow) * KL + (size_t)jb * 8;
    const u32 sRow = (u32)cRow * 128;
    u32 swz[4];
    #pragma unroll
    for (int j2 = 0; j2 < 4; ++j2)
        swz[j2] = (u32)(((jb + j2) ^ (cRow & 7)) << 4);

    // ---- ldmatrix per-lane bases: warp grid 2(M) x 4(N), tile 64x32 ----
    const int wm = (w >> 2) << 6;              // 0 or 64
    const int wn = (w & 3) << 5;               // 0,32,64,96
    const u32 raA = (u32)(wm + (lane & 15)) * 128;
    const u32 raB = (u32)(wn + (lane & 15)) * 128 + R_B;
    const u32 khalf = (u32)(lane >> 4);
    const u32 l7    = (u32)(lane & 7);

    float c[4][4][4] = {};
    u32 ah[2][4][4], bh[2][2][4];

    // ic is the LOCAL chunk index within this split (0..63).
    auto issue = [&](int ic) {
        if (ic < NCH_H) {
            const int icg = ic0 + ic;          // global chunk
            const u32 sdst = sb + (u32)(ic % NSTG) * STAGE;
            const size_t kbase = (size_t)(icg >> 4) * ((size_t)NT * KL)
                               + (size_t)((icg & 15) << 6);
            const __half* pa = gA + kbase;
            const __half* pb = gB + kbase;
            #pragma unroll
            for (int j2 = 0; j2 < 4; ++j2)
                cp16(sdst + sRow + swz[j2], pa + j2 * 8);
            #pragma unroll
            for (int j2 = 0; j2 < 4; ++j2)
                cp16(sdst + R_B + sRow + swz[j2], pb + j2 * 8);
        }
        asm volatile("cp.async.commit_group;" ::: "memory");
    };

    auto ldsm_kk = [&](u32 base, int kk, int fb) {
        const u32 off = (((u32)(2 * kk) + khalf) ^ l7) << 4;
        const u32 pa = base + raA + off;
        const u32 pb = base + raB + off;
        #pragma unroll
        for (int t = 0; t < 4; ++t) ldsm4(pa + (u32)t * 2048, ah[fb][t]);
        #pragma unroll
        for (int t = 0; t < 2; ++t) ldsm4(pb + (u32)t * 2048, bh[fb][t]);
    };

    // ---- prologue: stage chunks 0..1 of this split ----
    issue(0); issue(1);

    #pragma unroll 1
    for (int ic = 0; ic < NCH_H; ++ic) {
        const u32 base = sb + (u32)(ic % NSTG) * STAGE;

        // wait_group 1: all but the newest group complete -> chunk ic ready.
        // Barrier also fences readers of the slot issue() below overwrites
        // (slot (ic+2)%3 == (ic-1)%3, last read in iteration ic-1).
        asm volatile("cp.async.wait_group 1;" ::: "memory");
        __syncthreads();

        issue(ic + 2);

        ldsm_kk(base, 0, 0);
        #pragma unroll
        for (int kk = 0; kk < 4; ++kk) {
            const int fb = kk & 1;
            if (kk < 3) ldsm_kk(base, kk + 1, fb ^ 1);   // prefetch next block

            // mt -> j: same-accumulator dep distance = 16 MMAs
            #pragma unroll
            for (int mt = 0; mt < 4; ++mt) {
                #pragma unroll
                for (int j = 0; j < 4; ++j) {
                    const int t = j >> 1, s = j & 1;
                    mma16816(c[mt][j], ah[fb][mt], bh[fb][t][s], bh[fb][t][s + 2]);
                }
            }
        }
    }

    // ---- epilogue: atomic accumulate (two split contributors per tile) ----
    const int orow = m0 + wm + (lane >> 2);
    const int ocol = n0 + wn + ((lane & 3) << 1);
    #pragma unroll
    for (int mt = 0; mt < 4; ++mt) {
        #pragma unroll
        for (int j = 0; j < 4; ++j) {
            float* p = out + (size_t)(orow + mt * 16) * NT + (ocol + j * 8);
            atomicAdd(p,     c[mt][j][0]);
            atomicAdd(p + 1, c[mt][j][1]);
            atomicAdd(p + (size_t)8 * NT,     c[mt][j][2]);
            atomicAdd(p + (size_t)8 * NT + 1, c[mt][j][3]);
        }
    }
}

extern "C" void kernel_launch(void* const* d_in, const int* in_sizes, int n_in,
                              void* d_out, int out_size)
{
    const float* A = (const float*)d_in[0];   // [8, 4096, 1024]
    const float* W = (const float*)d_in[1];   // [8, 4096, 1024]
    float* out = (float*)d_out;               // [8, 512, 4096] == [4096, 4096]

    cvt_kernel<<<4096, 256>>>(A, W);
    zero_kernel<<<2048, 256>>>((float4*)out);

    cudaFuncSetAttribute(gemm_rs_kernel,
                         cudaFuncAttributeMaxDynamicSharedMemorySize, SMEM_TOTAL);
    gemm_rs_kernel<<<2048, 256, SMEM_TOTAL>>>(out);
}